// round 14
// baseline (speedup 1.0000x reference)
#include <cuda_runtime.h>
#include <cstdint>

// QuantumKANRegressor: out[b] = sum_f sum_j kan[f,j] * T_j( tanh( sum_k w[f,k]*T_{k+1}(X[b,f]) / sum_k|w[f,k]| ) )
// B=65536, F=64, DEG=16 (T_1..T_16), KAN_DEG=5 (T_0..T_5)
//
// R14 (= R13 resubmit; R13 bench died to broker infra failure):
// R12's even/odd Chebyshev split (validated), R=2 rows/group so register
// demand (~54) fits a 64-reg cap -> 4 CTAs/SM = 8 warps/SMSP.
// Measured: issue% tracks warps/SMSP (4w->26%, 6w->41%) with no pipe near
// saturation. Coefficients stay in SMEM planes (never spilled: R3/R9/R12).

typedef unsigned long long ull;

__device__ __forceinline__ ull pk2(float lo, float hi) {
    ull d; asm("mov.b64 %0, {%1, %2};" : "=l"(d) : "f"(lo), "f"(hi)); return d;
}
__device__ __forceinline__ void upk2(ull v, float& lo, float& hi) {
    asm("mov.b64 {%0, %1}, %2;" : "=f"(lo), "=f"(hi) : "l"(v));
}
__device__ __forceinline__ ull fma2(ull a, ull b, ull c) {
    ull d; asm("fma.rn.f32x2 %0, %1, %2, %3;" : "=l"(d) : "l"(a), "l"(b), "l"(c)); return d;
}
__device__ __forceinline__ ull add2(ull a, ull b) {
    ull d; asm("add.rn.f32x2 %0, %1, %2;" : "=l"(d) : "l"(a), "l"(b)); return d;
}
__device__ __forceinline__ ull mul2(ull a, ull b) {
    ull d; asm("mul.rn.f32x2 %0, %1, %2;" : "=l"(d) : "l"(a), "l"(b)); return d;
}
__device__ __forceinline__ float ex2f(float x) {
    float y; asm("ex2.approx.f32 %0, %1;" : "=f"(y) : "f"(x)); return y;
}
__device__ __forceinline__ float rcpf(float x) {
    float y; asm("rcp.approx.f32 %0, %1;" : "=f"(y) : "f"(x)); return y;
}
// tanh(f) = 1 - 2/(1 + exp(2f)); exp via ex2 (MUFU). ~1e-6 abs error on |f|<=1.
__device__ __forceinline__ float tanh_fast(float f) {
    float e = ex2f(f * 2.8853900817779268f);   // 2 * log2(e)
    float r = rcpf(e + 1.0f);
    return fmaf(-2.0f, r, 1.0f);
}

static constexpr int F    = 64;
static constexpr int NBLK = 592;   // 4 CTAs/SM * 148 SMs
static constexpr int NTHR = 256;

__global__ void __launch_bounds__(NTHR, 4)
qkan_kernel(const float* __restrict__ X,
            const float* __restrict__ W,    // [F, 16]
            const float* __restrict__ KC,   // [1, F, 6]
            float* __restrict__ out,        // [B]
            int B)
{
    // SMEM planes, lane-indexed, packed (f0=2*lane, f1=2*lane+1):
    //   ec_s[m-1][lane] = (E_m, C_m) for m=1..8 (C_8 = 0)  -> LDS.128
    //   c0_s[lane]      = C_0                               -> LDS.64
    //   pc_s[k][lane]   = KAN Horner coefficients           -> LDS.64
    __shared__ ulonglong2 ec_s[8][32];
    __shared__ ull c0_s[32];
    __shared__ ull pc_s[6][32];

    const int tid  = threadIdx.x;
    const int lane = tid & 31;

    if (tid < 32) {
        // ---- even/odd coefficient preprocessing (identical math to R12) ----
        // e_m (m=1..8): even orders 2m -> w[2m-1]; c_m: fold of odd orders via
        // T_{2m+1}(x) = x*(2T_m(y) - 2T_{m-1}(y) + ... +- T_0(y)).
        // Sign-folded recurrence S_m = s_m*T_m(y), s_m = -1 for m mod 4 in {2,3};
        // s folded into e, c.
        float ew[2][8], cw[2][8];
        #pragma unroll
        for (int i = 0; i < 2; ++i) {
            const int f = 2 * tid + i;
            float wv[16];
            float den = 0.0f;
            #pragma unroll
            for (int k = 0; k < 16; ++k) { wv[k] = __ldg(W + f * 16 + k); den += fabsf(wv[k]); }
            const float rd = 1.0f / den;
            #pragma unroll
            for (int m = 1; m <= 8; ++m) {
                float t = wv[2 * m - 1] * rd;      // even order 2m
                if (m & 2) t = -t;                 // fold s_m
                ew[i][m - 1] = t;
            }
            float s = 0.0f;
            #pragma unroll
            for (int m = 7; m >= 0; --m) {
                s = wv[2 * m] * rd - s;            // odd order 2m+1 suffix fold
                cw[i][m] = s;
            }
            #pragma unroll
            for (int m = 1; m <= 7; ++m) {
                float t = 2.0f * cw[i][m];
                if (m & 2) t = -t;                 // fold s_m
                cw[i][m] = t;
            }
        }
        #pragma unroll
        for (int m = 1; m <= 7; ++m)
            ec_s[m - 1][tid] = make_ulonglong2(pk2(ew[0][m - 1], ew[1][m - 1]),
                                               pk2(cw[0][m],     cw[1][m]));
        ec_s[7][tid] = make_ulonglong2(pk2(ew[0][7], ew[1][7]), 0ull);
        c0_s[tid]    = pk2(cw[0][0], cw[1][0]);

        // ---- KAN Chebyshev (deg 5) -> monomial Horner coefficients ----
        float pm[2][6];
        #pragma unroll
        for (int i = 0; i < 2; ++i) {
            const int f = 2 * tid + i;
            const float k0 = __ldg(KC + f*6+0), k1 = __ldg(KC + f*6+1), k2 = __ldg(KC + f*6+2);
            const float k3 = __ldg(KC + f*6+3), k4 = __ldg(KC + f*6+4), k5 = __ldg(KC + f*6+5);
            pm[i][0] = k0 - k2 + k4;
            pm[i][1] = k1 - 3.0f*k3 + 5.0f*k5;
            pm[i][2] = 2.0f*k2 - 8.0f*k4;
            pm[i][3] = 4.0f*k3 - 20.0f*k5;
            pm[i][4] = 8.0f*k4;
            pm[i][5] = 16.0f*k5;
        }
        #pragma unroll
        for (int k = 0; k < 6; ++k) pc_s[k][tid] = pk2(pm[0][k], pm[1][k]);
    }
    __syncthreads();

    const ull ONE2 = 0x3F8000003F800000ull;   // (1.0f, 1.0f)
    const ull NEG1 = 0xBF800000BF800000ull;   // (-1.0f, -1.0f)
    const ull NEG2 = 0xC0000000C0000000ull;   // (-2.0f, -2.0f)

    const int gw = (blockIdx.x * NTHR + tid) >> 5;
    const int nW = (gridDim.x * NTHR) >> 5;
    const int nG = B / 2;                      // 2 rows per group

    // X rows are 64 floats = 32 ulls; lane's packed feature pair is ull #lane.
    const ull* Xq = (const ull*)X;

    int g = gw;
    ull x0, x1;
    if (g < nG) {
        const ull* base = Xq + (size_t)(2 * g) * 32 + lane;
        x0 = __ldg(base);
        x1 = __ldg(base + 32);
    }

    while (g < nG) {
        const int gn = g + nW;
        ull nx0, nx1;
        if (gn < nG) {
            const ull* base = Xq + (size_t)(2 * gn) * 32 + lane;
            nx0 = __ldg(base);
            nx1 = __ldg(base + 32);
        }

        // ---- 2 independent chains, deg-8 recurrence in y = 2x^2 - 1 ----
        ull y0 = fma2(add2(x0, x0), x0, NEG1);
        ull y1 = fma2(add2(x1, x1), x1, NEG1);
        const ull p0 = add2(y0, y0),   p1 = add2(y1, y1);    // +2y
        const ull m0 = mul2(y0, NEG2), m1 = mul2(y1, NEG2);  // -2y
        ull sA0 = ONE2, sB0 = y0, sA1 = ONE2, sB1 = y1;
        ull aE0, aO0, aE1, aO1;
        {
            const ull c0 = c0_s[lane];
            const ulonglong2 ec1 = ec_s[0][lane];
            aE0 = mul2(ec1.x, y0);        aE1 = mul2(ec1.x, y1);
            aO0 = fma2(ec1.y, y0, c0);    aO1 = fma2(ec1.y, y1, c0);
        }
        #pragma unroll
        for (int mm = 2; mm <= 7; ++mm) {
            const ulonglong2 ec = ec_s[mm - 1][lane];
            const ull n0 = fma2((mm & 1) ? p0 : m0, sB0, sA0);
            const ull n1 = fma2((mm & 1) ? p1 : m1, sB1, sA1);
            aE0 = fma2(ec.x, n0, aE0);  aE1 = fma2(ec.x, n1, aE1);
            aO0 = fma2(ec.y, n0, aO0);  aO1 = fma2(ec.y, n1, aO1);
            sA0 = sB0; sB0 = n0;  sA1 = sB1; sB1 = n1;
        }
        {   // m = 8: even only
            const ulonglong2 ec = ec_s[7][lane];
            const ull n0 = fma2(m0, sB0, sA0);
            const ull n1 = fma2(m1, sB1, sA1);
            aE0 = fma2(ec.x, n0, aE0);  aE1 = fma2(ec.x, n1, aE1);
        }

        // feat = E + x*O; tanh (MUFU); deg-5 Horner (SMEM coeffs)
        const ull f0 = fma2(x0, aO0, aE0);
        const ull f1 = fma2(x1, aO1, aE1);
        float a0, b0, a1, b1;
        upk2(f0, a0, b0); upk2(f1, a1, b1);
        const ull z0 = pk2(tanh_fast(a0), tanh_fast(b0));
        const ull z1 = pk2(tanh_fast(a1), tanh_fast(b1));
        const ull q5 = pc_s[5][lane], q4 = pc_s[4][lane], q3 = pc_s[3][lane];
        const ull q2 = pc_s[2][lane], q1 = pc_s[1][lane], q0 = pc_s[0][lane];
        ull t0 = fma2(q5, z0, q4);
        ull t1 = fma2(q5, z1, q4);
        t0 = fma2(t0, z0, q3); t1 = fma2(t1, z1, q3);
        t0 = fma2(t0, z0, q2); t1 = fma2(t1, z1, q2);
        t0 = fma2(t0, z0, q1); t1 = fma2(t1, z1, q1);
        t0 = fma2(t0, z0, q0); t1 = fma2(t1, z1, q0);
        float s0lo, s0hi, s1lo, s1hi;
        upk2(t0, s0lo, s0hi); upk2(t1, s1lo, s1hi);
        const float s0 = s0lo + s0hi;          // row 2g   partial
        const float s1 = s1lo + s1hi;          // row 2g+1 partial

        // ---- warp reduction: pack (row0,row1), 5-level 64-bit tree ----
        {
            ull m = pk2(s0, s1);
            #pragma unroll
            for (int off = 16; off; off >>= 1)
                m = add2(m, __shfl_xor_sync(0xffffffffu, m, off));
            if (lane == 0) ((ull*)out)[g] = m;
        }

        x0 = nx0; x1 = nx1;
        g = gn;
    }
}

extern "C" void kernel_launch(void* const* d_in, const int* in_sizes, int n_in,
                              void* d_out, int out_size)
{
    const float* X  = (const float*)d_in[0];   // [B, 64] fp32
    const float* W  = (const float*)d_in[1];   // [64, 16] fp32
    const float* KC = (const float*)d_in[2];   // [1, 64, 6] fp32
    float* out = (float*)d_out;                // [B] fp32

    const int B = in_sizes[0] / F;             // 65536

    qkan_kernel<<<NBLK, NTHR>>>(X, W, KC, out, B);
}

// round 15
// speedup vs baseline: 1.0597x; 1.0597x over previous
#include <cuda_runtime.h>
#include <cstdint>

// QuantumKANRegressor: out[b] = sum_f sum_j kan[f,j] * T_j( tanh( sum_k w[f,k]*T_{k+1}(X[b,f]) / sum_k|w[f,k]| ) )
// B=65536, F=64, DEG=16 (T_1..T_16), KAN_DEG=5 (T_0..T_5)
//
// R15: cp.async 4-stage smem pipeline for X (DRAM latency fully decoupled at
// zero register cost; R12/R14 showed the binding stall is long-scoreboard on
// the X loads: dur tracked iteration-length latency coverage, not warp count).
// Compute core = R12's validated even/odd Chebyshev split, R=4 rows/warp,
// coefficients in SMEM planes, 3 CTAs/SM.

typedef unsigned long long ull;

__device__ __forceinline__ ull pk2(float lo, float hi) {
    ull d; asm("mov.b64 %0, {%1, %2};" : "=l"(d) : "f"(lo), "f"(hi)); return d;
}
__device__ __forceinline__ void upk2(ull v, float& lo, float& hi) {
    asm("mov.b64 {%0, %1}, %2;" : "=f"(lo), "=f"(hi) : "l"(v));
}
__device__ __forceinline__ ull fma2(ull a, ull b, ull c) {
    ull d; asm("fma.rn.f32x2 %0, %1, %2, %3;" : "=l"(d) : "l"(a), "l"(b), "l"(c)); return d;
}
__device__ __forceinline__ ull add2(ull a, ull b) {
    ull d; asm("add.rn.f32x2 %0, %1, %2;" : "=l"(d) : "l"(a), "l"(b)); return d;
}
__device__ __forceinline__ ull mul2(ull a, ull b) {
    ull d; asm("mul.rn.f32x2 %0, %1, %2;" : "=l"(d) : "l"(a), "l"(b)); return d;
}
__device__ __forceinline__ float ex2f(float x) {
    float y; asm("ex2.approx.f32 %0, %1;" : "=f"(y) : "f"(x)); return y;
}
__device__ __forceinline__ float rcpf(float x) {
    float y; asm("rcp.approx.f32 %0, %1;" : "=f"(y) : "f"(x)); return y;
}
// tanh(f) = 1 - 2/(1 + exp(2f)); exp via ex2 (MUFU). ~1e-6 abs error on |f|<=1.
__device__ __forceinline__ float tanh_fast(float f) {
    float e = ex2f(f * 2.8853900817779268f);   // 2 * log2(e)
    float r = rcpf(e + 1.0f);
    return fmaf(-2.0f, r, 1.0f);
}

__device__ __forceinline__ uint32_t smem_u32(const void* p) {
    uint32_t a;
    asm("{ .reg .u64 t; cvta.to.shared.u64 t, %1; cvt.u32.u64 %0, t; }" : "=r"(a) : "l"(p));
    return a;
}
__device__ __forceinline__ void cp16(uint32_t s, const void* g) {
    asm volatile("cp.async.cg.shared.global [%0], [%1], 16;" :: "r"(s), "l"(g));
}
#define CP_COMMIT() asm volatile("cp.async.commit_group;" ::: "memory")
#define CP_WAIT3()  asm volatile("cp.async.wait_group 3;"  ::: "memory")

static constexpr int F       = 64;
static constexpr int NBLK    = 444;    // 3 CTAs/SM * 148 SMs
static constexpr int NTHR    = 256;
static constexpr int UROWS   = 32;     // rows per unit (8 KB, contiguous in gmem)
static constexpr int NSTAGES = 4;

__global__ void __launch_bounds__(NTHR, 3)
qkan_kernel(const float* __restrict__ X,
            const float* __restrict__ W,    // [F, 16]
            const float* __restrict__ KC,   // [1, F, 6]
            float* __restrict__ out,        // [B]
            int B)
{
    // X staging ring: 4 stages x 32 rows x 32 ull = 32 KB. Row stride 32 ull
    // (256 B) -> lane-indexed LDS.64 across lanes is consecutive: conflict-free.
    __shared__ ull xs[NSTAGES][UROWS * 32];
    // Coefficient planes (validated R12 layout).
    __shared__ ulonglong2 ec_s[8][32];
    __shared__ ull c0_s[32];
    __shared__ ull pc_s[6][32];

    const int tid  = threadIdx.x;
    const int lane = tid & 31;
    const int wid  = tid >> 5;            // 0..7

    if (tid < 32) {
        // ---- even/odd coefficient preprocessing (identical math to R12) ----
        float ew[2][8], cw[2][8];
        #pragma unroll
        for (int i = 0; i < 2; ++i) {
            const int f = 2 * tid + i;
            float wv[16];
            float den = 0.0f;
            #pragma unroll
            for (int k = 0; k < 16; ++k) { wv[k] = __ldg(W + f * 16 + k); den += fabsf(wv[k]); }
            const float rd = 1.0f / den;
            #pragma unroll
            for (int m = 1; m <= 8; ++m) {
                float t = wv[2 * m - 1] * rd;      // even order 2m
                if (m & 2) t = -t;                 // fold s_m
                ew[i][m - 1] = t;
            }
            float s = 0.0f;
            #pragma unroll
            for (int m = 7; m >= 0; --m) {
                s = wv[2 * m] * rd - s;            // odd order 2m+1 suffix fold
                cw[i][m] = s;
            }
            #pragma unroll
            for (int m = 1; m <= 7; ++m) {
                float t = 2.0f * cw[i][m];
                if (m & 2) t = -t;                 // fold s_m
                cw[i][m] = t;
            }
        }
        #pragma unroll
        for (int m = 1; m <= 7; ++m)
            ec_s[m - 1][tid] = make_ulonglong2(pk2(ew[0][m - 1], ew[1][m - 1]),
                                               pk2(cw[0][m],     cw[1][m]));
        ec_s[7][tid] = make_ulonglong2(pk2(ew[0][7], ew[1][7]), 0ull);
        c0_s[tid]    = pk2(cw[0][0], cw[1][0]);

        // ---- KAN Chebyshev (deg 5) -> monomial Horner coefficients ----
        float pm[2][6];
        #pragma unroll
        for (int i = 0; i < 2; ++i) {
            const int f = 2 * tid + i;
            const float k0 = __ldg(KC + f*6+0), k1 = __ldg(KC + f*6+1), k2 = __ldg(KC + f*6+2);
            const float k3 = __ldg(KC + f*6+3), k4 = __ldg(KC + f*6+4), k5 = __ldg(KC + f*6+5);
            pm[i][0] = k0 - k2 + k4;
            pm[i][1] = k1 - 3.0f*k3 + 5.0f*k5;
            pm[i][2] = 2.0f*k2 - 8.0f*k4;
            pm[i][3] = 4.0f*k3 - 20.0f*k5;
            pm[i][4] = 8.0f*k4;
            pm[i][5] = 16.0f*k5;
        }
        #pragma unroll
        for (int k = 0; k < 6; ++k) pc_s[k][tid] = pk2(pm[0][k], pm[1][k]);
    }

    const int nU = B / UROWS;               // 2048 units

    // ---- pipeline prologue: issue first NSTAGES units ----
    const uint32_t xs_base = smem_u32(&xs[0][0]);
    #pragma unroll
    for (int i = 0; i < NSTAGES; ++i) {
        const int uu = blockIdx.x + i * gridDim.x;
        if (uu < nU) {
            const char* src = (const char*)X + (size_t)uu * (UROWS * 256);
            const uint32_t dst = xs_base + i * (UROWS * 256);
            cp16(dst + tid * 16,        src + tid * 16);
            cp16(dst + 4096 + tid * 16, src + 4096 + tid * 16);
        }
        CP_COMMIT();
    }
    __syncthreads();   // coefficient planes ready (overlaps with cp.async flight)

    const ull ONE2 = 0x3F8000003F800000ull;   // (1.0f, 1.0f)
    const ull NEG1 = 0xBF800000BF800000ull;   // (-1.0f, -1.0f)
    const ull NEG2 = 0xC0000000C0000000ull;   // (-2.0f, -2.0f)

    int stage = 0;
    for (int u = blockIdx.x; u < nU; u += gridDim.x) {
        CP_WAIT3();          // oldest stage's copies complete (this thread's)
        __syncthreads();     // ...and everyone else's

        // ---- compute: warp handles rows 4*wid .. 4*wid+3 of this unit ----
        const ull* xrow = &xs[stage][(4 * wid) * 32 + lane];
        ull x[4];
        #pragma unroll
        for (int r = 0; r < 4; ++r) x[r] = xrow[r * 32];

        ull y[4], p[4], m_[4], sA[4], sB[4], aE[4], aO[4];
        {
            const ull c0 = c0_s[lane];
            const ulonglong2 ec1 = ec_s[0][lane];
            #pragma unroll
            for (int r = 0; r < 4; ++r) {
                y[r]  = fma2(add2(x[r], x[r]), x[r], NEG1);   // y = 2x^2 - 1
                p[r]  = add2(y[r], y[r]);                     // +2y
                m_[r] = mul2(y[r], NEG2);                     // -2y
                sA[r] = ONE2;
                sB[r] = y[r];
                aE[r] = mul2(ec1.x, y[r]);
                aO[r] = fma2(ec1.y, y[r], c0);
            }
        }
        #pragma unroll
        for (int mm = 2; mm <= 7; ++mm) {
            const ulonglong2 ec = ec_s[mm - 1][lane];
            #pragma unroll
            for (int r = 0; r < 4; ++r) {
                const ull n = fma2((mm & 1) ? p[r] : m_[r], sB[r], sA[r]);
                aE[r] = fma2(ec.x, n, aE[r]);
                aO[r] = fma2(ec.y, n, aO[r]);
                sA[r] = sB[r]; sB[r] = n;
            }
        }
        {   // m = 8: even only
            const ulonglong2 ec = ec_s[7][lane];
            #pragma unroll
            for (int r = 0; r < 4; ++r) {
                const ull n = fma2(m_[r], sB[r], sA[r]);
                aE[r] = fma2(ec.x, n, aE[r]);
            }
        }

        // feat = E + x*O; tanh (MUFU); deg-5 Horner
        ull z[4];
        #pragma unroll
        for (int r = 0; r < 4; ++r) {
            const ull f = fma2(x[r], aO[r], aE[r]);
            float lo, hi; upk2(f, lo, hi);
            z[r] = pk2(tanh_fast(lo), tanh_fast(hi));
        }
        const ull q5 = pc_s[5][lane], q4 = pc_s[4][lane], q3 = pc_s[3][lane];
        const ull q2 = pc_s[2][lane], q1 = pc_s[1][lane], q0 = pc_s[0][lane];
        float s[4];
        #pragma unroll
        for (int r = 0; r < 4; ++r) {
            ull t = fma2(q5, z[r], q4);
            t = fma2(t, z[r], q3);
            t = fma2(t, z[r], q2);
            t = fma2(t, z[r], q1);
            t = fma2(t, z[r], q0);
            float lo, hi; upk2(t, lo, hi);
            s[r] = lo + hi;
        }

        // ---- folded warp reduction: 4 rows -> 2 packed values, 5 levels ----
        {
            const ull A  = pk2(s[0], s[1]);
            const ull Bp = pk2(s[2], s[3]);
            ull acc = (lane & 16) ? Bp : A;
            ull oth = (lane & 16) ? A  : Bp;
            acc = add2(acc, __shfl_xor_sync(0xffffffffu, oth, 16));
            #pragma unroll
            for (int off = 8; off; off >>= 1)
                acc = add2(acc, __shfl_xor_sync(0xffffffffu, acc, off));
            if ((lane & 15) == 0) {
                // unit u, warp wid, half (lane>>4): rows (32u+4wid) .. +3
                ((ull*)out)[16 * u + 2 * wid + (lane >> 4)] = acc;
            }
        }

        __syncthreads();     // all warps done reading this stage

        // ---- refill this stage with unit u + NSTAGES*stride ----
        {
            const int uu = u + NSTAGES * gridDim.x;
            if (uu < nU) {
                const char* src = (const char*)X + (size_t)uu * (UROWS * 256);
                const uint32_t dst = xs_base + stage * (UROWS * 256);
                cp16(dst + tid * 16,        src + tid * 16);
                cp16(dst + 4096 + tid * 16, src + 4096 + tid * 16);
            }
            CP_COMMIT();     // commit even when empty: keeps group accounting aligned
        }
        stage = (stage + 1) & (NSTAGES - 1);
    }
}

extern "C" void kernel_launch(void* const* d_in, const int* in_sizes, int n_in,
                              void* d_out, int out_size)
{
    const float* X  = (const float*)d_in[0];   // [B, 64] fp32
    const float* W  = (const float*)d_in[1];   // [64, 16] fp32
    const float* KC = (const float*)d_in[2];   // [1, 64, 6] fp32
    float* out = (float*)d_out;                // [B] fp32

    const int B = in_sizes[0] / F;             // 65536

    qkan_kernel<<<NBLK, NTHR>>>(X, W, KC, out, B);
}

// round 17
// speedup vs baseline: 1.0618x; 1.0019x over previous
#include <cuda_runtime.h>
#include <cstdint>

// QuantumKANRegressor: out[b] = sum_f sum_j kan[f,j] * T_j( tanh( sum_k w[f,k]*T_{k+1}(X[b,f]) / sum_k|w[f,k]| ) )
// B=65536, F=64, DEG=16 (T_1..T_16), KAN_DEG=5 (T_0..T_5)
//
// R17 = R12 (best: 15.7us) + software-pipelined reduction: the 5-level
// SHFL64 tree of group g-1 executes inside the same basic block as group g's
// ~100-instruction fma chain, so ptxas interleaves and the ~150-cycle serial
// shfl tail disappears from the warp's critical path. (R16's redux.sync.f32
// is unavailable: harness compiles via compute_100, not compute_100a.)
// Loop is peeled: first group compute-only; epilogue reduces the last group.

typedef unsigned long long ull;

__device__ __forceinline__ ull pk2(float lo, float hi) {
    ull d; asm("mov.b64 %0, {%1, %2};" : "=l"(d) : "f"(lo), "f"(hi)); return d;
}
__device__ __forceinline__ void upk2(ull v, float& lo, float& hi) {
    asm("mov.b64 {%0, %1}, %2;" : "=f"(lo), "=f"(hi) : "l"(v));
}
__device__ __forceinline__ ull fma2(ull a, ull b, ull c) {
    ull d; asm("fma.rn.f32x2 %0, %1, %2, %3;" : "=l"(d) : "l"(a), "l"(b), "l"(c)); return d;
}
__device__ __forceinline__ ull add2(ull a, ull b) {
    ull d; asm("add.rn.f32x2 %0, %1, %2;" : "=l"(d) : "l"(a), "l"(b)); return d;
}
__device__ __forceinline__ ull mul2(ull a, ull b) {
    ull d; asm("mul.rn.f32x2 %0, %1, %2;" : "=l"(d) : "l"(a), "l"(b)); return d;
}
__device__ __forceinline__ float ex2f(float x) {
    float y; asm("ex2.approx.f32 %0, %1;" : "=f"(y) : "f"(x)); return y;
}
__device__ __forceinline__ float rcpf(float x) {
    float y; asm("rcp.approx.f32 %0, %1;" : "=f"(y) : "f"(x)); return y;
}
// tanh(f) = 1 - 2/(1 + exp(2f)); exp via ex2 (MUFU). ~1e-6 abs error on |f|<=1.
__device__ __forceinline__ float tanh_fast(float f) {
    float e = ex2f(f * 2.8853900817779268f);   // 2 * log2(e)
    float r = rcpf(e + 1.0f);
    return fmaf(-2.0f, r, 1.0f);
}

static constexpr int F    = 64;
static constexpr int NBLK = 444;   // 3 CTAs/SM * 148 SMs
static constexpr int NTHR = 256;
static constexpr int R    = 4;     // rows per warp-iteration

// ---- compute 4 rows' per-lane partials (R12's validated even/odd core) ----
__device__ __forceinline__ void compute_group(
    const ull x[R], float s[R], int lane,
    const ulonglong2 (*ec_s)[32], const ull* c0_s, const ull (*pc_s)[32])
{
    const ull ONE2 = 0x3F8000003F800000ull;
    const ull NEG1 = 0xBF800000BF800000ull;
    const ull NEG2 = 0xC0000000C0000000ull;

    ull y[R], p[R], m_[R], sA[R], sB[R], aE[R], aO[R];
    {
        const ull c0 = c0_s[lane];
        const ulonglong2 ec1 = ec_s[0][lane];
        #pragma unroll
        for (int r = 0; r < R; ++r) {
            y[r]  = fma2(add2(x[r], x[r]), x[r], NEG1);   // y = 2x^2 - 1
            p[r]  = add2(y[r], y[r]);                     // +2y
            m_[r] = mul2(y[r], NEG2);                     // -2y
            sA[r] = ONE2;
            sB[r] = y[r];
            aE[r] = mul2(ec1.x, y[r]);
            aO[r] = fma2(ec1.y, y[r], c0);
        }
    }
    #pragma unroll
    for (int mm = 2; mm <= 7; ++mm) {
        const ulonglong2 ec = ec_s[mm - 1][lane];
        #pragma unroll
        for (int r = 0; r < R; ++r) {
            const ull n = fma2((mm & 1) ? p[r] : m_[r], sB[r], sA[r]);
            aE[r] = fma2(ec.x, n, aE[r]);
            aO[r] = fma2(ec.y, n, aO[r]);
            sA[r] = sB[r]; sB[r] = n;
        }
    }
    {   // m = 8: even only
        const ulonglong2 ec = ec_s[7][lane];
        #pragma unroll
        for (int r = 0; r < R; ++r) {
            const ull n = fma2(m_[r], sB[r], sA[r]);
            aE[r] = fma2(ec.x, n, aE[r]);
        }
    }
    // feat = E + x*O; tanh (MUFU); deg-5 Horner
    ull z[R];
    #pragma unroll
    for (int r = 0; r < R; ++r) {
        const ull f = fma2(x[r], aO[r], aE[r]);
        float lo, hi; upk2(f, lo, hi);
        z[r] = pk2(tanh_fast(lo), tanh_fast(hi));
    }
    const ull q5 = pc_s[5][lane], q4 = pc_s[4][lane], q3 = pc_s[3][lane];
    const ull q2 = pc_s[2][lane], q1 = pc_s[1][lane], q0 = pc_s[0][lane];
    #pragma unroll
    for (int r = 0; r < R; ++r) {
        ull t = fma2(q5, z[r], q4);
        t = fma2(t, z[r], q3);
        t = fma2(t, z[r], q2);
        t = fma2(t, z[r], q1);
        t = fma2(t, z[r], q0);
        float lo, hi; upk2(t, lo, hi);
        s[r] = lo + hi;
    }
}

// ---- folded 5-level reduction + store for a previous group's partials ----
__device__ __forceinline__ void reduce_store(
    ull A, ull Bp, int gprev, int lane, float* out)
{
    ull acc = (lane & 16) ? Bp : A;
    ull oth = (lane & 16) ? A  : Bp;
    acc = add2(acc, __shfl_xor_sync(0xffffffffu, oth, 16));
    #pragma unroll
    for (int off = 8; off; off >>= 1)
        acc = add2(acc, __shfl_xor_sync(0xffffffffu, acc, off));
    if ((lane & 15) == 0)
        ((ull*)out)[2 * gprev + (lane >> 4)] = acc;
}

__global__ void __launch_bounds__(NTHR, 3)
qkan_kernel(const float* __restrict__ X,
            const float* __restrict__ W,    // [F, 16]
            const float* __restrict__ KC,   // [1, F, 6]
            float* __restrict__ out,        // [B]
            int B)
{
    __shared__ ulonglong2 ec_s[8][32];
    __shared__ ull c0_s[32];
    __shared__ ull pc_s[6][32];

    const int tid  = threadIdx.x;
    const int lane = tid & 31;

    if (tid < 32) {
        // ---- even/odd coefficient preprocessing (identical math to R12) ----
        float ew[2][8], cw[2][8];
        #pragma unroll
        for (int i = 0; i < 2; ++i) {
            const int f = 2 * tid + i;
            float wv[16];
            float den = 0.0f;
            #pragma unroll
            for (int k = 0; k < 16; ++k) { wv[k] = __ldg(W + f * 16 + k); den += fabsf(wv[k]); }
            const float rd = 1.0f / den;
            #pragma unroll
            for (int m = 1; m <= 8; ++m) {
                float t = wv[2 * m - 1] * rd;      // even order 2m
                if (m & 2) t = -t;                 // fold s_m
                ew[i][m - 1] = t;
            }
            float s = 0.0f;
            #pragma unroll
            for (int m = 7; m >= 0; --m) {
                s = wv[2 * m] * rd - s;            // odd order 2m+1 suffix fold
                cw[i][m] = s;
            }
            #pragma unroll
            for (int m = 1; m <= 7; ++m) {
                float t = 2.0f * cw[i][m];
                if (m & 2) t = -t;                 // fold s_m
                cw[i][m] = t;
            }
        }
        #pragma unroll
        for (int m = 1; m <= 7; ++m)
            ec_s[m - 1][tid] = make_ulonglong2(pk2(ew[0][m - 1], ew[1][m - 1]),
                                               pk2(cw[0][m],     cw[1][m]));
        ec_s[7][tid] = make_ulonglong2(pk2(ew[0][7], ew[1][7]), 0ull);
        c0_s[tid]    = pk2(cw[0][0], cw[1][0]);

        // ---- KAN Chebyshev (deg 5) -> monomial Horner coefficients ----
        float pm[2][6];
        #pragma unroll
        for (int i = 0; i < 2; ++i) {
            const int f = 2 * tid + i;
            const float k0 = __ldg(KC + f*6+0), k1 = __ldg(KC + f*6+1), k2 = __ldg(KC + f*6+2);
            const float k3 = __ldg(KC + f*6+3), k4 = __ldg(KC + f*6+4), k5 = __ldg(KC + f*6+5);
            pm[i][0] = k0 - k2 + k4;
            pm[i][1] = k1 - 3.0f*k3 + 5.0f*k5;
            pm[i][2] = 2.0f*k2 - 8.0f*k4;
            pm[i][3] = 4.0f*k3 - 20.0f*k5;
            pm[i][4] = 8.0f*k4;
            pm[i][5] = 16.0f*k5;
        }
        #pragma unroll
        for (int k = 0; k < 6; ++k) pc_s[k][tid] = pk2(pm[0][k], pm[1][k]);
    }
    __syncthreads();

    const int gw = (blockIdx.x * NTHR + tid) >> 5;
    const int nW = (gridDim.x * NTHR) >> 5;
    const int nG = B / R;                      // B % 4 == 0

    const ull* Xq = (const ull*)X;

    int g = gw;
    if (g >= nG) return;

    // ---- peeled first group: load + compute, no reduction yet ----
    ull x[R];
    {
        const ull* base = Xq + (size_t)(R * g) * 32 + lane;
        #pragma unroll
        for (int r = 0; r < R; ++r) x[r] = __ldg(base + r * 32);
    }
    ull redA, redB;
    int gprev;
    {
        const int gn = g + nW;
        ull nx[R];
        if (gn < nG) {
            const ull* base = Xq + (size_t)(R * gn) * 32 + lane;
            #pragma unroll
            for (int r = 0; r < R; ++r) nx[r] = __ldg(base + r * 32);
        }
        float s[R];
        compute_group(x, s, lane, ec_s, c0_s, pc_s);
        redA = pk2(s[0], s[1]);
        redB = pk2(s[2], s[3]);
        gprev = g;
        #pragma unroll
        for (int r = 0; r < R; ++r) x[r] = nx[r];
        g = gn;
    }

    // ---- steady state: compute group g while reducing group gprev ----
    while (g < nG) {
        const int gn = g + nW;
        ull nx[R];
        if (gn < nG) {
            const ull* base = Xq + (size_t)(R * gn) * 32 + lane;
            #pragma unroll
            for (int r = 0; r < R; ++r) nx[r] = __ldg(base + r * 32);
        }

        float s[R];
        compute_group(x, s, lane, ec_s, c0_s, pc_s);

        // Reduction of the PREVIOUS group: independent of the fma chain above;
        // same basic block -> ptxas interleaves shfl issues among the fma2s.
        reduce_store(redA, redB, gprev, lane, out);

        redA = pk2(s[0], s[1]);
        redB = pk2(s[2], s[3]);
        gprev = g;
        #pragma unroll
        for (int r = 0; r < R; ++r) x[r] = nx[r];
        g = gn;
    }

    // ---- epilogue: reduce the final group ----
    reduce_store(redA, redB, gprev, lane, out);
}

extern "C" void kernel_launch(void* const* d_in, const int* in_sizes, int n_in,
                              void* d_out, int out_size)
{
    const float* X  = (const float*)d_in[0];   // [B, 64] fp32
    const float* W  = (const float*)d_in[1];   // [64, 16] fp32
    const float* KC = (const float*)d_in[2];   // [1, 64, 6] fp32
    float* out = (float*)d_out;                // [B] fp32

    const int B = in_sizes[0] / F;             // 65536

    qkan_kernel<<<NBLK, NTHR>>>(X, W, KC, out, B);
}